// round 5
// baseline (speedup 1.0000x reference)
#include <cuda_runtime.h>

// HyperComplexAdapterBlock: y = phm_up(gelu_new(phm_down(x))), rank-1 PHM.
// R5: NO smem staging. Lane l directly loads/stores its 24 contiguous
// floats (float4 idx 6l..6l+5) of each token — 32-sector "uncoalesced"
// accesses are cheaper (48 cyc/tok) than stage-transpose (72 cyc/tok) and
// DRAM-sector-exact. Output computed in transposed layout (lane's outputs
// all in group c=g) -> zero output shuffles. All weights in padded
// conflict-free smem; fused [Rd,Lu] float2 table; tanh.approx gelu.

typedef unsigned long long u64;

__device__ __forceinline__ u64 fma2(u64 a, u64 b, u64 c) {
    u64 d;
    asm("fma.rn.f32x2 %0, %1, %2, %3;" : "=l"(d) : "l"(a), "l"(b), "l"(c));
    return d;
}
__device__ __forceinline__ u64 pk2(float lo, float hi) {
    u64 r; asm("mov.b64 %0, {%1, %2};" : "=l"(r) : "f"(lo), "f"(hi));
    return r;
}
__device__ __forceinline__ float sum2(u64 v) {
    float a, b; asm("mov.b64 {%0, %1}, %2;" : "=f"(a), "=f"(b) : "l"(v));
    return a + b;
}
__device__ __forceinline__ float tanh_fast(float x) {
    float y; asm("tanh.approx.f32 %0, %1;" : "=f"(y) : "f"(x));
    return y;
}

#define NW 4          // warps per CTA
#define NT 128        // threads per CTA
#define TPI 4         // tokens per warp-iteration

__global__ __launch_bounds__(NT, 5)
void phm_fused_kernel(const float* __restrict__ x,
                      const float* __restrict__ rule_d,
                      const float* __restrict__ Ld,
                      const float* __restrict__ Rd,
                      const float* __restrict__ bd,
                      const float* __restrict__ rule_u,
                      const float* __restrict__ Lu,
                      const float* __restrict__ Ru,
                      const float* __restrict__ bu,
                      float* __restrict__ out,
                      int ntok)
{
    // padded, conflict-free weight tables
    __shared__ ulonglong2 pLd [4*8*7];   // [(i*8+k)*7 + j] <- Ld4[i*48+6k+j]
    __shared__ ulonglong2 pRu [4*8*7];   // same layout for Ru
    __shared__ float2     pRL [4*8*9];   // [(i*8+k)*9 + j] = (Rd, Lu)[i*48+6k+j]
    __shared__ ulonglong2 sBuT[32*7];    // [l*7 + j] <- bu4[6l+j]
    __shared__ float      sRd[64], sRu[64];

    const int tid = threadIdx.x;
    const ulonglong2* Ld2 = (const ulonglong2*)Ld;
    const ulonglong2* Ru2 = (const ulonglong2*)Ru;
    const ulonglong2* bu2 = (const ulonglong2*)bu;

    for (int idx = tid; idx < 192; idx += NT) {
        int i = idx / 48, r = idx % 48, kk = r / 6, j = r % 6;
        pLd[(i*8 + kk)*7 + j] = Ld2[idx];
        pRu[(i*8 + kk)*7 + j] = Ru2[idx];
        pRL[(i*8 + kk)*9 + j] = make_float2(Rd[idx], Lu[idx]);
        sBuT[(idx/6)*7 + (idx%6)] = bu2[idx];
    }
    for (int idx = tid; idx < 64; idx += NT) {
        sRd[idx] = rule_d[idx];
        sRu[idx] = rule_u[idx];
    }
    __syncthreads();

    const int l = tid & 31;
    const int w = tid >> 5;
    const int g = l >> 3;        // group: a on input side, c on z/output side
    const int k = l & 7;

    float biasD[6];
#pragma unroll
    for (int j = 0; j < 6; j++)
        biasD[j] = bd[6*l + j];

    const ulonglong2* x2 = (const ulonglong2*)x;
    ulonglong2*       o2 = (ulonglong2*)out;

    const int gwarp = blockIdx.x * NW + w;
    const int nwarp = gridDim.x * NW;

    for (int base = gwarp * TPI; base < ntok; base += nwarp * TPI) {
        // ---- down stage 1: direct transposed global loads + packed FMA ----
        u64 si2[TPI][4];
#pragma unroll
        for (int tt = 0; tt < TPI; tt++)
#pragma unroll
            for (int i = 0; i < 4; i++) si2[tt][i] = 0ull;

#pragma unroll
        for (int j = 0; j < 6; j++) {
            ulonglong2 u[TPI];
#pragma unroll
            for (int tt = 0; tt < TPI; tt++) {
                int t = base + tt; if (t > ntok - 1) t = ntok - 1;
                u[tt] = x2[(size_t)t * 192 + 6*l + j];
            }
#pragma unroll
            for (int i = 0; i < 4; i++) {
                ulonglong2 wv = pLd[(i*8 + k)*7 + j];
#pragma unroll
                for (int tt = 0; tt < TPI; tt++) {
                    si2[tt][i] = fma2(u[tt].x, wv.x, si2[tt][i]);
                    si2[tt][i] = fma2(u[tt].y, wv.y, si2[tt][i]);
                }
            }
        }
        float si[TPI][4];
#pragma unroll
        for (int tt = 0; tt < TPI; tt++)
#pragma unroll
            for (int i = 0; i < 4; i++) {
                float v = sum2(si2[tt][i]);
                v += __shfl_xor_sync(0xffffffffu, v, 4);
                v += __shfl_xor_sync(0xffffffffu, v, 2);
                v += __shfl_xor_sync(0xffffffffu, v, 1);
                si[tt][i] = v;
            }

        // ---- down stage 2: t[c][i] (c = g) ----
        float tD[TPI][4];
#pragma unroll
        for (int tt = 0; tt < TPI; tt++)
#pragma unroll
            for (int i = 0; i < 4; i++) tD[tt][i] = 0.f;
#pragma unroll
        for (int a = 0; a < 4; a++)
#pragma unroll
            for (int i = 0; i < 4; i++) {
                float r = sRd[i*16 + a*4 + g];
#pragma unroll
                for (int tt = 0; tt < TPI; tt++)
                    tD[tt][i] = fmaf(r, __shfl_sync(0xffffffffu, si[tt][i], a*8 + k),
                                     tD[tt][i]);
            }

        // ---- fused z -> gelu_new -> up stage 1 (s2) ----
        float s2[TPI][4];
#pragma unroll
        for (int tt = 0; tt < TPI; tt++)
#pragma unroll
            for (int i = 0; i < 4; i++) s2[tt][i] = 0.f;

#pragma unroll
        for (int j = 0; j < 6; j++) {
            float2 rl[4];
#pragma unroll
            for (int i = 0; i < 4; i++) rl[i] = pRL[(i*8 + k)*9 + j];
            float zv[TPI];
#pragma unroll
            for (int tt = 0; tt < TPI; tt++) zv[tt] = biasD[j];
#pragma unroll
            for (int i = 0; i < 4; i++)
#pragma unroll
                for (int tt = 0; tt < TPI; tt++)
                    zv[tt] = fmaf(tD[tt][i], rl[i].x, zv[tt]);
#pragma unroll
            for (int tt = 0; tt < TPI; tt++) {
                float z   = zv[tt];
                float arg = 0.7978845608028654f * fmaf(0.044715f*z, z*z, z);
                float h   = 0.5f * z;
                zv[tt] = fmaf(h, tanh_fast(arg), h);   // 0.5z(1+tanh)
            }
#pragma unroll
            for (int i = 0; i < 4; i++)
#pragma unroll
                for (int tt = 0; tt < TPI; tt++)
                    s2[tt][i] = fmaf(zv[tt], rl[i].y, s2[tt][i]);
        }
#pragma unroll
        for (int tt = 0; tt < TPI; tt++)
#pragma unroll
            for (int i = 0; i < 4; i++) {
                float v = s2[tt][i];
                v += __shfl_xor_sync(0xffffffffu, v, 4);
                v += __shfl_xor_sync(0xffffffffu, v, 2);
                v += __shfl_xor_sync(0xffffffffu, v, 1);
                s2[tt][i] = v;
            }

        // ---- up stage 2: tU[c][i] (c = g), packed for output ----
        u64 tUp[TPI][4];
#pragma unroll
        for (int tt = 0; tt < TPI; tt++)
#pragma unroll
            for (int i = 0; i < 4; i++) {
                float acc = 0.f;
#pragma unroll
                for (int a = 0; a < 4; a++)
                    acc = fmaf(sRu[i*16 + a*4 + g],
                               __shfl_sync(0xffffffffu, s2[tt][i], a*8 + k), acc);
                tUp[tt][i] = pk2(acc, acc);
            }

        // ---- output: transposed direct stores (lane owns f4 6l..6l+5) ----
#pragma unroll
        for (int j = 0; j < 6; j++) {
            ulonglong2 bb = sBuT[l*7 + j];
            ulonglong2 rv[4];
#pragma unroll
            for (int i = 0; i < 4; i++) rv[i] = pRu[(i*8 + k)*7 + j];
#pragma unroll
            for (int tt = 0; tt < TPI; tt++) {
                ulonglong2 o = bb;
#pragma unroll
                for (int i = 0; i < 4; i++) {
                    o.x = fma2(tUp[tt][i], rv[i].x, o.x);
                    o.y = fma2(tUp[tt][i], rv[i].y, o.y);
                }
                if (base + tt < ntok)
                    o2[(size_t)(base + tt) * 192 + 6*l + j] = o;
            }
        }
    }
}

extern "C" void kernel_launch(void* const* d_in, const int* in_sizes, int n_in,
                              void* d_out, int out_size)
{
    const float* x      = (const float*)d_in[0];
    const float* rule_d = (const float*)d_in[1];
    const float* Ld     = (const float*)d_in[2];
    const float* Rd     = (const float*)d_in[3];
    const float* bd     = (const float*)d_in[4];
    const float* rule_u = (const float*)d_in[5];
    const float* Lu     = (const float*)d_in[6];
    const float* Ru     = (const float*)d_in[7];
    const float* bu     = (const float*)d_in[8];

    const int ntok = in_sizes[0] / 768;

    // 148 SMs * 5 CTAs (128 thr) persistent, grid-stride over token quads
    phm_fused_kernel<<<740, NT>>>(x, rule_d, Ld, Rd, bd,
                                  rule_u, Lu, Ru, bu,
                                  (float*)d_out, ntok);
}

// round 6
// speedup vs baseline: 1.5768x; 1.5768x over previous
#include <cuda_runtime.h>

// HyperComplexAdapterBlock: y = phm_up(gelu_new(phm_down(x))), rank-1 PHM.
// R6 = R4 pipeline + transposed-output compute (no output shuffles, no
// scattered weight reads) + out-stage through the same swizzled smem buffer
// for fully-coalesced STG (R5 showed strided STG causes L2 RMW -> +75% DRAM
// traffic). Bias_u added at the coalesced stage-read via packed add.f32x2
// from L1-cached __ldg. gelu via tanh.approx (validated 5.6e-7 rel_err).

typedef unsigned long long u64;

__device__ __forceinline__ u64 fma2(u64 a, u64 b, u64 c) {
    u64 d;
    asm("fma.rn.f32x2 %0, %1, %2, %3;" : "=l"(d) : "l"(a), "l"(b), "l"(c));
    return d;
}
__device__ __forceinline__ u64 add2(u64 a, u64 b) {
    u64 d;
    asm("add.rn.f32x2 %0, %1, %2;" : "=l"(d) : "l"(a), "l"(b));
    return d;
}
__device__ __forceinline__ u64 pk2(float lo, float hi) {
    u64 r; asm("mov.b64 %0, {%1, %2};" : "=l"(r) : "f"(lo), "f"(hi));
    return r;
}
__device__ __forceinline__ float sum2(u64 v) {
    float a, b; asm("mov.b64 {%0, %1}, %2;" : "=f"(a), "=f"(b) : "l"(v));
    return a + b;
}
__device__ __forceinline__ float tanh_fast(float x) {
    float y; asm("tanh.approx.f32 %0, %1;" : "=f"(y) : "f"(x));
    return y;
}

#define NW 4          // warps per CTA
#define NT 128        // threads per CTA
#define TPI 3         // tokens per warp-iteration
#define SW(f) ((f) ^ (((f) >> 3) & 1))

// dynamic smem layout (bytes)
#define OFF_STG   0
#define SZ_STG    (NW * TPI * 192 * 16)           // 36864
#define OFF_PLD   (OFF_STG + SZ_STG)              // 192 f4 XOR-swizzled
#define OFF_PRU   (OFF_PLD + 3072)                // 192 f4 XOR-swizzled
#define OFF_PRL   (OFF_PRU + 3072)                // 192 float2 (Rd,Lu) plain
#define OFF_RRD   (OFF_PRL + 1536)                // 64 f rule_d
#define OFF_RRU   (OFF_RRD + 256)                 // 64 f rule_u
#define SMEM_TOTAL (OFF_RRU + 256)                // 45056

__global__ __launch_bounds__(NT, 5)
void phm_fused_kernel(const float* __restrict__ x,
                      const float* __restrict__ rule_d,
                      const float* __restrict__ Ld,
                      const float* __restrict__ Rd,
                      const float* __restrict__ bd,
                      const float* __restrict__ rule_u,
                      const float* __restrict__ Lu,
                      const float* __restrict__ Ru,
                      const float* __restrict__ bu,
                      float* __restrict__ out,
                      int ntok)
{
    extern __shared__ __align__(16) char smem[];
    ulonglong2* stg  = (ulonglong2*)(smem + OFF_STG);
    ulonglong2* pLd2 = (ulonglong2*)(smem + OFF_PLD);
    ulonglong2* pRu2 = (ulonglong2*)(smem + OFF_PRU);
    float2*     pRL  = (float2*)(smem + OFF_PRL);
    float*      sRd  = (float*)(smem + OFF_RRD);
    float*      sRu  = (float*)(smem + OFF_RRU);

    const int tid = threadIdx.x;
    const ulonglong2* Ld2 = (const ulonglong2*)Ld;
    const ulonglong2* Ru2 = (const ulonglong2*)Ru;
    const ulonglong2* bu2 = (const ulonglong2*)bu;

    for (int idx = tid; idx < 192; idx += NT) {
        pLd2[SW(idx)] = Ld2[idx];
        pRu2[SW(idx)] = Ru2[idx];
        pRL [idx]     = make_float2(Rd[idx], Lu[idx]);
    }
    for (int idx = tid; idx < 64; idx += NT) {
        sRd[idx] = rule_d[idx];
        sRu[idx] = rule_u[idx];
    }
    __syncthreads();

    const int l = tid & 31;
    const int w = tid >> 5;
    const int g = l >> 3;        // group: a on input side, c on z/output side
    const int k = l & 7;

    float biasD[6];
#pragma unroll
    for (int j = 0; j < 6; j++)
        biasD[j] = bd[6*l + j];

    int wsl[6], rsl[6], rwk[6];
#pragma unroll
    for (int j = 0; j < 6; j++) {
        wsl[j] = SW(l + 32*j);   // coalesced stage side
        rsl[j] = SW(6*l + j);    // transposed stage side
        rwk[j] = SW(6*k + j);    // swizzled weight slice (per-k, bcast x4)
    }

    const ulonglong2* x2 = (const ulonglong2*)x;
    ulonglong2*       o2 = (ulonglong2*)out;
    ulonglong2* stgW = stg + (size_t)w * (TPI * 192);

    const int gwarp = blockIdx.x * NW + w;
    const int nwarp = gridDim.x * NW;

    for (int base = gwarp * TPI; base < ntok; base += nwarp * TPI) {
        // ---- stage in: TPI tokens, coalesced LDG.128 -> swizzled STS ----
        __syncwarp();
#pragma unroll
        for (int tt = 0; tt < TPI; tt++) {
            int t = base + tt; if (t > ntok - 1) t = ntok - 1;
            const ulonglong2* xr = x2 + (size_t)t * 192;
#pragma unroll
            for (int j = 0; j < 6; j++)
                stgW[tt*192 + wsl[j]] = xr[l + 32*j];
        }
        __syncwarp();

        // ---- down stage 1: si partials (packed f32x2, weights bcast) ----
        u64 si2[TPI][4];
#pragma unroll
        for (int tt = 0; tt < TPI; tt++)
#pragma unroll
            for (int i = 0; i < 4; i++) si2[tt][i] = 0ull;

#pragma unroll
        for (int j = 0; j < 6; j++) {
            ulonglong2 u[TPI];
#pragma unroll
            for (int tt = 0; tt < TPI; tt++)
                u[tt] = stgW[tt*192 + rsl[j]];
#pragma unroll
            for (int i = 0; i < 4; i++) {
                ulonglong2 wv = pLd2[i*48 + rwk[j]];
#pragma unroll
                for (int tt = 0; tt < TPI; tt++) {
                    si2[tt][i] = fma2(u[tt].x, wv.x, si2[tt][i]);
                    si2[tt][i] = fma2(u[tt].y, wv.y, si2[tt][i]);
                }
            }
        }
        float si[TPI][4];
#pragma unroll
        for (int tt = 0; tt < TPI; tt++)
#pragma unroll
            for (int i = 0; i < 4; i++) {
                float v = sum2(si2[tt][i]);
                v += __shfl_xor_sync(0xffffffffu, v, 4);
                v += __shfl_xor_sync(0xffffffffu, v, 2);
                v += __shfl_xor_sync(0xffffffffu, v, 1);
                si[tt][i] = v;
            }

        // ---- down stage 2: t[c][i] (c = g) ----
        float tD[TPI][4];
#pragma unroll
        for (int tt = 0; tt < TPI; tt++)
#pragma unroll
            for (int i = 0; i < 4; i++) tD[tt][i] = 0.f;
#pragma unroll
        for (int a = 0; a < 4; a++)
#pragma unroll
            for (int i = 0; i < 4; i++) {
                float r = sRd[i*16 + a*4 + g];
#pragma unroll
                for (int tt = 0; tt < TPI; tt++)
                    tD[tt][i] = fmaf(r, __shfl_sync(0xffffffffu, si[tt][i], a*8 + k),
                                     tD[tt][i]);
            }

        // ---- fused z -> gelu_new -> up stage 1 (s2) ----
        float s2[TPI][4];
#pragma unroll
        for (int tt = 0; tt < TPI; tt++)
#pragma unroll
            for (int i = 0; i < 4; i++) s2[tt][i] = 0.f;

#pragma unroll
        for (int j = 0; j < 6; j++) {
            float2 rl[4];
#pragma unroll
            for (int i = 0; i < 4; i++) rl[i] = pRL[i*48 + 6*k + j];
            float zv[TPI];
#pragma unroll
            for (int tt = 0; tt < TPI; tt++) zv[tt] = biasD[j];
#pragma unroll
            for (int i = 0; i < 4; i++)
#pragma unroll
                for (int tt = 0; tt < TPI; tt++)
                    zv[tt] = fmaf(tD[tt][i], rl[i].x, zv[tt]);
#pragma unroll
            for (int tt = 0; tt < TPI; tt++) {
                float z   = zv[tt];
                float arg = 0.7978845608028654f * fmaf(0.044715f*z, z*z, z);
                float h   = 0.5f * z;
                zv[tt] = fmaf(h, tanh_fast(arg), h);   // 0.5z(1+tanh)
            }
#pragma unroll
            for (int i = 0; i < 4; i++)
#pragma unroll
                for (int tt = 0; tt < TPI; tt++)
                    s2[tt][i] = fmaf(zv[tt], rl[i].y, s2[tt][i]);
        }
#pragma unroll
        for (int tt = 0; tt < TPI; tt++)
#pragma unroll
            for (int i = 0; i < 4; i++) {
                float v = s2[tt][i];
                v += __shfl_xor_sync(0xffffffffu, v, 4);
                v += __shfl_xor_sync(0xffffffffu, v, 2);
                v += __shfl_xor_sync(0xffffffffu, v, 1);
                s2[tt][i] = v;
            }

        // ---- up stage 2: tU[c][i] (c = g), packed for output ----
        u64 tUp[TPI][4];
#pragma unroll
        for (int tt = 0; tt < TPI; tt++)
#pragma unroll
            for (int i = 0; i < 4; i++) {
                float acc = 0.f;
#pragma unroll
                for (int a = 0; a < 4; a++)
                    acc = fmaf(sRu[i*16 + a*4 + g],
                               __shfl_sync(0xffffffffu, s2[tt][i], a*8 + k), acc);
                tUp[tt][i] = pk2(acc, acc);
            }

        // ---- output: transposed compute (lane owns f4 6l..6l+5, no SHFL,
        //      broadcast weights) -> swizzled STS -> coalesced LDS+bias+STG
        __syncwarp();   // x-stage reads complete before overwrite
#pragma unroll
        for (int j = 0; j < 6; j++) {
            ulonglong2 rv[4];
#pragma unroll
            for (int i = 0; i < 4; i++) rv[i] = pRu2[i*48 + rwk[j]];
#pragma unroll
            for (int tt = 0; tt < TPI; tt++) {
                ulonglong2 o; o.x = 0ull; o.y = 0ull;
#pragma unroll
                for (int i = 0; i < 4; i++) {
                    o.x = fma2(tUp[tt][i], rv[i].x, o.x);
                    o.y = fma2(tUp[tt][i], rv[i].y, o.y);
                }
                stgW[tt*192 + rsl[j]] = o;
            }
        }
        __syncwarp();
#pragma unroll
        for (int j = 0; j < 6; j++) {
            ulonglong2 bb = __ldg(&bu2[l + 32*j]);   // L1-resident after iter 1
#pragma unroll
            for (int tt = 0; tt < TPI; tt++) {
                if (base + tt < ntok) {
                    ulonglong2 v = stgW[tt*192 + wsl[j]];
                    v.x = add2(v.x, bb.x);
                    v.y = add2(v.y, bb.y);
                    o2[(size_t)(base + tt) * 192 + l + 32*j] = v;
                }
            }
        }
    }
}

extern "C" void kernel_launch(void* const* d_in, const int* in_sizes, int n_in,
                              void* d_out, int out_size)
{
    const float* x      = (const float*)d_in[0];
    const float* rule_d = (const float*)d_in[1];
    const float* Ld     = (const float*)d_in[2];
    const float* Rd     = (const float*)d_in[3];
    const float* bd     = (const float*)d_in[4];
    const float* rule_u = (const float*)d_in[5];
    const float* Lu     = (const float*)d_in[6];
    const float* Ru     = (const float*)d_in[7];
    const float* bu     = (const float*)d_in[8];

    const int ntok = in_sizes[0] / 768;

    cudaFuncSetAttribute(phm_fused_kernel,
                         cudaFuncAttributeMaxDynamicSharedMemorySize,
                         SMEM_TOTAL);

    // 148 SMs * 5 CTAs (128 thr, 44KB smem each) = one full wave
    phm_fused_kernel<<<740, NT, SMEM_TOTAL>>>(x, rule_d, Ld, Rd, bd,
                                              rule_u, Lu, Ru, bu,
                                              (float*)d_out, ntok);
}